// round 1
// baseline (speedup 1.0000x reference)
#include <cuda_runtime.h>

// Scratch (no allocations allowed — device globals)
__device__ float g_A2[1024 * 256];     // a' = x@Wg[:D] + bg
__device__ float g_B2[1024 * 256];     // b  = x@Wg[D:]
__device__ float g_paccv[256 * 256];   // per (b*64+ib) partial: sum_{i,j} rs*v_h
__device__ float g_psrm[256];          // per (b*64+ib) partial: sum_{i,j} rs*m
__device__ float g_rel[4 * 256];       // final rel vector per batch

// ---------------------------------------------------------------------------
// Kernel A: a' = x @ Wg[:256] + bg ; b = x @ Wg[256:]
// grid (64, 2), block 256. Each block: 16 rows x 256 cols, z selects half.
// ---------------------------------------------------------------------------
__global__ __launch_bounds__(256) void gemm_ab(const float* __restrict__ x,
                                               const float* __restrict__ Wg,
                                               const float* __restrict__ bg) {
    int z = blockIdx.y;
    int m0 = blockIdx.x * 16;
    const float* __restrict__ W = Wg + z * 65536;   // Wg[(z*256+d)*256 + h]
    __shared__ float xs[16][256];
    int tid = threadIdx.x;
#pragma unroll
    for (int r = 0; r < 16; r++) xs[r][tid] = x[(m0 + r) * 256 + tid];
    __syncthreads();

    float acc[16];
    float bias = (z == 0) ? bg[tid] : 0.0f;
#pragma unroll
    for (int r = 0; r < 16; r++) acc[r] = bias;

#pragma unroll 4
    for (int d = 0; d < 256; d++) {
        float w = W[d * 256 + tid];
        const float4* xr = reinterpret_cast<const float4*>(&xs[0][0]);
        // broadcast loads of xs[r][d]
#pragma unroll
        for (int r = 0; r < 16; r++) acc[r] = fmaf(xs[r][d], w, acc[r]);
        (void)xr;
    }

    float* __restrict__ out = z ? g_B2 : g_A2;
#pragma unroll
    for (int r = 0; r < 16; r++) out[(m0 + r) * 256 + tid] = acc[r];
}

// ---------------------------------------------------------------------------
// Kernel B: pair loop. grid (64 i-tiles, 4 batches), block 256 (8 warps).
// Each block handles i in [ib*4, ib*4+4) x all j. Warp w takes j = w, w+8, ...
// Lane l owns h = 8l..8l+7 (two float4s). Accumulates:
//   acc_h  += rs_ij * relu(a'_ih + b_jh)      (over its pairs)
//   srm    += rs_ij * m_ij
// Deterministic per-block partials written to g_paccv / g_psrm (no atomics).
// ---------------------------------------------------------------------------
__global__ __launch_bounds__(256) void pair_kernel() {
    int b = blockIdx.y;
    int ib = blockIdx.x;
    int warp = threadIdx.x >> 5;
    int lane = threadIdx.x & 31;

    const float4* __restrict__ Abase =
        reinterpret_cast<const float4*>(g_A2 + (b * 256 + ib * 4) * 256);
    float4 a0[4], a1[4];
#pragma unroll
    for (int ii = 0; ii < 4; ii++) {
        a0[ii] = Abase[ii * 64 + lane * 2];
        a1[ii] = Abase[ii * 64 + lane * 2 + 1];
    }

    const float4* __restrict__ Bb =
        reinterpret_cast<const float4*>(g_B2 + b * 65536);

    float acc[8] = {0.f, 0.f, 0.f, 0.f, 0.f, 0.f, 0.f, 0.f};
    float srm = 0.0f;

#pragma unroll 2
    for (int j = warp; j < 256; j += 8) {
        float4 b0 = Bb[j * 64 + lane * 2];
        float4 b1 = Bb[j * 64 + lane * 2 + 1];
#pragma unroll
        for (int ii = 0; ii < 4; ii++) {
            float v[8];
            v[0] = fmaxf(a0[ii].x + b0.x, 0.0f);
            v[1] = fmaxf(a0[ii].y + b0.y, 0.0f);
            v[2] = fmaxf(a0[ii].z + b0.z, 0.0f);
            v[3] = fmaxf(a0[ii].w + b0.w, 0.0f);
            v[4] = fmaxf(a1[ii].x + b1.x, 0.0f);
            v[5] = fmaxf(a1[ii].y + b1.y, 0.0f);
            v[6] = fmaxf(a1[ii].z + b1.z, 0.0f);
            v[7] = fmaxf(a1[ii].w + b1.w, 0.0f);

            float s1 = ((v[0] + v[1]) + (v[2] + v[3])) +
                       ((v[4] + v[5]) + (v[6] + v[7]));
            float s2a = fmaf(v[0], v[0], v[1] * v[1]);
            float s2b = fmaf(v[2], v[2], v[3] * v[3]);
            float s2c = fmaf(v[4], v[4], v[5] * v[5]);
            float s2d = fmaf(v[6], v[6], v[7] * v[7]);
            float s2 = (s2a + s2b) + (s2c + s2d);

#pragma unroll
            for (int off = 16; off > 0; off >>= 1) {
                s1 += __shfl_xor_sync(0xffffffffu, s1, off);
                s2 += __shfl_xor_sync(0xffffffffu, s2, off);
            }
            float m = s1 * (1.0f / 256.0f);
            float var = fmaf(s2, 1.0f / 256.0f, -m * m);
            float rs = rsqrtf(var + 1e-5f);
#pragma unroll
            for (int k = 0; k < 8; k++) acc[k] = fmaf(rs, v[k], acc[k]);
            srm = fmaf(rs, m, srm);
        }
    }

    // Block reduction across the 8 warps (deterministic order).
    __shared__ float sacc[8][256];
    __shared__ float ssrm[8];
    float4* srow = reinterpret_cast<float4*>(&sacc[warp][0]);
    srow[lane * 2]     = make_float4(acc[0], acc[1], acc[2], acc[3]);
    srow[lane * 2 + 1] = make_float4(acc[4], acc[5], acc[6], acc[7]);
    if (lane == 0) ssrm[warp] = srm;
    __syncthreads();

    int tid = threadIdx.x;
    float tot = 0.0f;
#pragma unroll
    for (int w = 0; w < 8; w++) tot += sacc[w][tid];
    g_paccv[(b * 64 + ib) * 256 + tid] = tot;
    if (tid == 0) {
        float s = 0.0f;
#pragma unroll
        for (int w = 0; w < 8; w++) s += ssrm[w];
        g_psrm[b * 64 + ib] = s;
    }
}

// ---------------------------------------------------------------------------
// Kernel C: reduce partials -> r_sum, matvec with Wf, relu, LN -> g_rel.
// grid 4 (one block per batch), block 256.
// ---------------------------------------------------------------------------
__global__ __launch_bounds__(256) void finalize(const float* __restrict__ Wf,
                                                const float* __restrict__ bfv,
                                                const float* __restrict__ g_gamma,
                                                const float* __restrict__ g_beta,
                                                const float* __restrict__ f_gamma,
                                                const float* __restrict__ f_beta) {
    int b = blockIdx.x;
    int h = threadIdx.x;
    __shared__ float rsum[256];
    __shared__ float ssr[64];

    float av = 0.0f;
#pragma unroll 8
    for (int ib = 0; ib < 64; ib++) av += g_paccv[(b * 64 + ib) * 256 + h];
    if (h < 64) ssr[h] = g_psrm[b * 64 + h];
    __syncthreads();

    float srm = 0.0f;
#pragma unroll
    for (int q = 0; q < 64; q++) srm += ssr[q];

    // r_sum_h = gamma*(sum rs*v - sum rs*m) + Npairs*beta
    rsum[h] = g_gamma[h] * (av - srm) + 65536.0f * g_beta[h];
    __syncthreads();

    float y = bfv[h];
#pragma unroll 8
    for (int d = 0; d < 256; d++) y = fmaf(rsum[d], Wf[d * 256 + h], y);
    y = fmaxf(y, 0.0f);

    // block LayerNorm over the 256 y values
    float s1 = y, s2 = y * y;
#pragma unroll
    for (int off = 16; off > 0; off >>= 1) {
        s1 += __shfl_xor_sync(0xffffffffu, s1, off);
        s2 += __shfl_xor_sync(0xffffffffu, s2, off);
    }
    __shared__ float w1[8], w2[8];
    int warp = h >> 5, lane = h & 31;
    if (lane == 0) { w1[warp] = s1; w2[warp] = s2; }
    __syncthreads();
    float S1 = 0.0f, S2 = 0.0f;
#pragma unroll
    for (int w = 0; w < 8; w++) { S1 += w1[w]; S2 += w2[w]; }
    float m = S1 * (1.0f / 256.0f);
    float var = fmaf(S2, 1.0f / 256.0f, -m * m);
    float rs = rsqrtf(var + 1e-5f);
    g_rel[b * 256 + h] = (y - m) * rs * f_gamma[h] + f_beta[h];
}

// ---------------------------------------------------------------------------
// Kernel D: out[b,n,:] = rel[b,:] + x[b,n,:]  (vectorized float4)
// ---------------------------------------------------------------------------
__global__ __launch_bounds__(256) void add_out(const float* __restrict__ x,
                                               float* __restrict__ out) {
    int i4 = blockIdx.x * 256 + threadIdx.x;  // 0..65535 float4s
    int base = i4 * 4;
    int b = base >> 16;       // 256*256 elems per batch
    int d = base & 255;
    float4 xv = reinterpret_cast<const float4*>(x)[i4];
    float4 rv = *reinterpret_cast<const float4*>(g_rel + b * 256 + d);
    float4 o;
    o.x = xv.x + rv.x;
    o.y = xv.y + rv.y;
    o.z = xv.z + rv.z;
    o.w = xv.w + rv.w;
    reinterpret_cast<float4*>(out)[i4] = o;
}

// ---------------------------------------------------------------------------
extern "C" void kernel_launch(void* const* d_in, const int* in_sizes, int n_in,
                              void* d_out, int out_size) {
    const float* x       = (const float*)d_in[0];
    const float* Wg      = (const float*)d_in[1];
    const float* bg      = (const float*)d_in[2];
    const float* g_gamma = (const float*)d_in[3];
    const float* g_beta  = (const float*)d_in[4];
    const float* Wf      = (const float*)d_in[5];
    const float* bf      = (const float*)d_in[6];
    const float* f_gamma = (const float*)d_in[7];
    const float* f_beta  = (const float*)d_in[8];
    float* out = (float*)d_out;

    gemm_ab<<<dim3(64, 2), 256>>>(x, Wg, bg);
    pair_kernel<<<dim3(64, 4), 256>>>();
    finalize<<<4, 256>>>(Wf, bf, g_gamma, g_beta, f_gamma, f_beta);
    add_out<<<256, 256>>>(x, out);
}

// round 2
// speedup vs baseline: 1.1108x; 1.1108x over previous
#include <cuda_runtime.h>

typedef unsigned long long u64;

// ---- f32x2 packed helpers (sm_100+/sm_103a) --------------------------------
__device__ __forceinline__ u64 pk2(float lo, float hi) {
    u64 r; asm("mov.b64 %0, {%1,%2};" : "=l"(r) : "f"(lo), "f"(hi)); return r;
}
__device__ __forceinline__ void up2(u64 v, float& lo, float& hi) {
    asm("mov.b64 {%0,%1}, %2;" : "=f"(lo), "=f"(hi) : "l"(v));
}
__device__ __forceinline__ u64 addx2(u64 a, u64 b) {
    u64 r; asm("add.rn.f32x2 %0, %1, %2;" : "=l"(r) : "l"(a), "l"(b)); return r;
}
__device__ __forceinline__ u64 mulx2(u64 a, u64 b) {
    u64 r; asm("mul.rn.f32x2 %0, %1, %2;" : "=l"(r) : "l"(a), "l"(b)); return r;
}
__device__ __forceinline__ u64 fmax2p(u64 a, u64 b, u64 c) {
    u64 r; asm("fma.rn.f32x2 %0, %1, %2, %3;" : "=l"(r) : "l"(a), "l"(b), "l"(c)); return r;
}

// ---- scratch (device globals; no allocs allowed) ---------------------------
__device__ float g_A2[1024 * 256];     // a' = x@Wg[:D] + bg
__device__ float g_B2[1024 * 256];     // b  = x@Wg[D:]
__device__ float g_paccv[512 * 256];   // per (b,ib,jh) partial: sum rs*v_h
__device__ float g_psrm[512];          // per (b,ib,jh) partial: sum rs*m
__device__ float g_rel[4 * 256];       // final rel vector per batch

// ---------------------------------------------------------------------------
// Kernel A: a' = x @ Wg[:256] + bg ; b = x @ Wg[256:]
// grid (64, 2), block 256. 16 rows x 256 cols per block, FFMA2 over row pairs.
// ---------------------------------------------------------------------------
__global__ __launch_bounds__(256) void gemm_ab(const float* __restrict__ x,
                                               const float* __restrict__ Wg,
                                               const float* __restrict__ bg) {
    int z = blockIdx.y;
    int m0 = blockIdx.x * 16;
    const float* __restrict__ W = Wg + z * 65536;   // Wg[(z*256+d)*256 + h]
    __shared__ float xst[256][20];                  // d-major, padded (rows 0..15)
    int tid = threadIdx.x;
#pragma unroll
    for (int r = 0; r < 16; r++) xst[tid][r] = x[(m0 + r) * 256 + tid];
    __syncthreads();

    float bias = (z == 0) ? bg[tid] : 0.0f;
    u64 accp[8];
#pragma unroll
    for (int k = 0; k < 8; k++) accp[k] = pk2(bias, bias);

#pragma unroll 4
    for (int d = 0; d < 256; d++) {
        float w = W[d * 256 + tid];
        u64 wp = pk2(w, w);
        const u64* xr = reinterpret_cast<const u64*>(&xst[d][0]);
#pragma unroll
        for (int k = 0; k < 8; k++) accp[k] = fmax2p(xr[k], wp, accp[k]);
    }

    float* __restrict__ out = z ? g_B2 : g_A2;
#pragma unroll
    for (int k = 0; k < 8; k++) {
        float o0, o1;
        up2(accp[k], o0, o1);
        out[(m0 + 2 * k) * 256 + tid] = o0;
        out[(m0 + 2 * k + 1) * 256 + tid] = o1;
    }
}

// ---------------------------------------------------------------------------
// Kernel B: pair loop. grid (64 ib, 4 b, 2 jh), block 256 (8 warps).
// Block: i in [ib*4, ib*4+4) x j in [jh*128, jh*128+128). Warp w: j=w, w+8,...
// Lane l owns h = 8l..8l+7 (4 packed f32x2). Per pair: relu+LN stats via
// packed math, warp butterfly on packed (s1,s2), then acc += rs*v (FFMA2).
// Deterministic per-block partials -> g_paccv / g_psrm.
// ---------------------------------------------------------------------------
__global__ __launch_bounds__(256) void pair_kernel() {
    int ib = blockIdx.x;
    int b  = blockIdx.y;
    int jh = blockIdx.z;
    int warp = threadIdx.x >> 5;
    int lane = threadIdx.x & 31;

    const ulonglong2* __restrict__ Ab =
        reinterpret_cast<const ulonglong2*>(g_A2 + (b * 256 + ib * 4) * 256);
    u64 ap[4][4];
#pragma unroll
    for (int ii = 0; ii < 4; ii++) {
        ulonglong2 t0 = Ab[ii * 64 + lane * 2];
        ulonglong2 t1 = Ab[ii * 64 + lane * 2 + 1];
        ap[ii][0] = t0.x; ap[ii][1] = t0.y; ap[ii][2] = t1.x; ap[ii][3] = t1.y;
    }

    const ulonglong2* __restrict__ Bb =
        reinterpret_cast<const ulonglong2*>(g_B2 + b * 65536);

    u64 acc[4];
#pragma unroll
    for (int k = 0; k < 4; k++) acc[k] = pk2(0.0f, 0.0f);
    float srm = 0.0f;

    int jbase = jh * 128 + warp;
#pragma unroll 2
    for (int jt = 0; jt < 16; jt++) {
        int j = jbase + jt * 8;
        ulonglong2 t0 = Bb[j * 64 + lane * 2];
        ulonglong2 t1 = Bb[j * 64 + lane * 2 + 1];
        u64 bp[4] = {t0.x, t0.y, t1.x, t1.y};

#pragma unroll
        for (int ii = 0; ii < 4; ii++) {
            u64 pre[4];
#pragma unroll
            for (int k = 0; k < 4; k++) pre[k] = addx2(ap[ii][k], bp[k]);

            float v[8];
#pragma unroll
            for (int k = 0; k < 4; k++) {
                float p0, p1;
                up2(pre[k], p0, p1);
                v[2 * k]     = fmaxf(p0, 0.0f);   // FMNMX (alu pipe)
                v[2 * k + 1] = fmaxf(p1, 0.0f);
            }
            u64 vp[4];
#pragma unroll
            for (int k = 0; k < 4; k++) vp[k] = pk2(v[2 * k], v[2 * k + 1]);

            // s1 = sum v ; s2 = sum v^2 (packed trees)
            u64 s1p = addx2(addx2(vp[0], vp[1]), addx2(vp[2], vp[3]));
            float sa, sb; up2(s1p, sa, sb);
            float s1 = sa + sb;

            u64 q = mulx2(vp[0], vp[0]);
            q = fmax2p(vp[1], vp[1], q);
            q = fmax2p(vp[2], vp[2], q);
            q = fmax2p(vp[3], vp[3], q);
            float qa, qb; up2(q, qa, qb);
            float s2 = qa + qb;

            // warp butterfly on packed (s1, s2)
            u64 s = pk2(s1, s2);
#pragma unroll
            for (int off = 16; off > 0; off >>= 1) {
                u64 o = __shfl_xor_sync(0xffffffffu, s, off);
                s = addx2(s, o);
            }
            float S1, S2; up2(s, S1, S2);

            float m   = S1 * (1.0f / 256.0f);
            float var = fmaf(S2, 1.0f / 256.0f, -m * m);
            float rs  = rsqrtf(var + 1e-5f);
            u64 rsp = pk2(rs, rs);
#pragma unroll
            for (int k = 0; k < 4; k++) acc[k] = fmax2p(vp[k], rsp, acc[k]);
            srm = fmaf(rs, m, srm);
        }
    }

    // Block reduction across 8 warps (deterministic order).
    __shared__ float sacc[8][256];
    __shared__ float ssrm[8];
    {
        float o[8];
#pragma unroll
        for (int k = 0; k < 4; k++) up2(acc[k], o[2 * k], o[2 * k + 1]);
        float4* srow = reinterpret_cast<float4*>(&sacc[warp][0]);
        srow[lane * 2]     = make_float4(o[0], o[1], o[2], o[3]);
        srow[lane * 2 + 1] = make_float4(o[4], o[5], o[6], o[7]);
        if (lane == 0) ssrm[warp] = srm;
    }
    __syncthreads();

    int tid = threadIdx.x;
    float tot = 0.0f;
#pragma unroll
    for (int w = 0; w < 8; w++) tot += sacc[w][tid];
    int p = (b * 64 + ib) * 2 + jh;
    g_paccv[p * 256 + tid] = tot;
    if (tid == 0) {
        float s = 0.0f;
#pragma unroll
        for (int w = 0; w < 8; w++) s += ssrm[w];
        g_psrm[p] = s;
    }
}

// ---------------------------------------------------------------------------
// Kernel C: reduce partials -> r_sum, matvec with Wf, relu, LN -> g_rel.
// grid 4, block 256.
// ---------------------------------------------------------------------------
__global__ __launch_bounds__(256) void finalize(const float* __restrict__ Wf,
                                                const float* __restrict__ bfv,
                                                const float* __restrict__ g_gamma,
                                                const float* __restrict__ g_beta,
                                                const float* __restrict__ f_gamma,
                                                const float* __restrict__ f_beta) {
    int b = blockIdx.x;
    int h = threadIdx.x;
    __shared__ float rsum[256];
    __shared__ float ssr[128];

    float av = 0.0f;
#pragma unroll 8
    for (int p = 0; p < 128; p++) av += g_paccv[(b * 128 + p) * 256 + h];
    if (h < 128) ssr[h] = g_psrm[b * 128 + h];
    __syncthreads();

    float srm = 0.0f;
#pragma unroll
    for (int q = 0; q < 128; q++) srm += ssr[q];

    // r_sum_h = gamma*(sum rs*v - sum rs*m) + Npairs*beta
    rsum[h] = g_gamma[h] * (av - srm) + 65536.0f * g_beta[h];
    __syncthreads();

    float y = bfv[h];
#pragma unroll 8
    for (int d = 0; d < 256; d++) y = fmaf(rsum[d], Wf[d * 256 + h], y);
    y = fmaxf(y, 0.0f);

    float s1 = y, s2 = y * y;
#pragma unroll
    for (int off = 16; off > 0; off >>= 1) {
        s1 += __shfl_xor_sync(0xffffffffu, s1, off);
        s2 += __shfl_xor_sync(0xffffffffu, s2, off);
    }
    __shared__ float w1[8], w2[8];
    int warp = h >> 5, lane = h & 31;
    if (lane == 0) { w1[warp] = s1; w2[warp] = s2; }
    __syncthreads();
    float S1 = 0.0f, S2 = 0.0f;
#pragma unroll
    for (int w = 0; w < 8; w++) { S1 += w1[w]; S2 += w2[w]; }
    float m = S1 * (1.0f / 256.0f);
    float var = fmaf(S2, 1.0f / 256.0f, -m * m);
    float rs = rsqrtf(var + 1e-5f);
    g_rel[b * 256 + h] = (y - m) * rs * f_gamma[h] + f_beta[h];
}

// ---------------------------------------------------------------------------
// Kernel D: out[b,n,:] = rel[b,:] + x[b,n,:]
// ---------------------------------------------------------------------------
__global__ __launch_bounds__(128) void add_out(const float* __restrict__ x,
                                               float* __restrict__ out) {
    int i4 = blockIdx.x * 128 + threadIdx.x;  // 0..65535 float4s
    int base = i4 * 4;
    int b = base >> 16;
    int d = base & 255;
    float4 xv = reinterpret_cast<const float4*>(x)[i4];
    float4 rv = *reinterpret_cast<const float4*>(g_rel + b * 256 + d);
    float4 o;
    o.x = xv.x + rv.x;
    o.y = xv.y + rv.y;
    o.z = xv.z + rv.z;
    o.w = xv.w + rv.w;
    reinterpret_cast<float4*>(out)[i4] = o;
}

// ---------------------------------------------------------------------------
extern "C" void kernel_launch(void* const* d_in, const int* in_sizes, int n_in,
                              void* d_out, int out_size) {
    const float* x       = (const float*)d_in[0];
    const float* Wg      = (const float*)d_in[1];
    const float* bg      = (const float*)d_in[2];
    const float* g_gamma = (const float*)d_in[3];
    const float* g_beta  = (const float*)d_in[4];
    const float* Wf      = (const float*)d_in[5];
    const float* bf      = (const float*)d_in[6];
    const float* f_gamma = (const float*)d_in[7];
    const float* f_beta  = (const float*)d_in[8];
    float* out = (float*)d_out;

    gemm_ab<<<dim3(64, 2), 256>>>(x, Wg, bg);
    pair_kernel<<<dim3(64, 4, 2), 256>>>();
    finalize<<<4, 256>>>(Wf, bf, g_gamma, g_beta, f_gamma, f_beta);
    add_out<<<512, 128>>>(x, out);
}

// round 3
// speedup vs baseline: 1.4771x; 1.3297x over previous
#include <cuda_runtime.h>

typedef unsigned long long u64;

// ---- f32x2 packed helpers (sm_103a) ----------------------------------------
__device__ __forceinline__ u64 pk2(float lo, float hi) {
    u64 r; asm("mov.b64 %0, {%1,%2};" : "=l"(r) : "f"(lo), "f"(hi)); return r;
}
__device__ __forceinline__ void up2(u64 v, float& lo, float& hi) {
    asm("mov.b64 {%0,%1}, %2;" : "=f"(lo), "=f"(hi) : "l"(v));
}
__device__ __forceinline__ u64 addx2(u64 a, u64 b) {
    u64 r; asm("add.rn.f32x2 %0, %1, %2;" : "=l"(r) : "l"(a), "l"(b)); return r;
}
__device__ __forceinline__ u64 mulx2(u64 a, u64 b) {
    u64 r; asm("mul.rn.f32x2 %0, %1, %2;" : "=l"(r) : "l"(a), "l"(b)); return r;
}
__device__ __forceinline__ u64 fmax2p(u64 a, u64 b, u64 c) {
    u64 r; asm("fma.rn.f32x2 %0, %1, %2, %3;" : "=l"(r) : "l"(a), "l"(b), "l"(c)); return r;
}

// ---- scratch (device globals; no allocs allowed) ---------------------------
__device__ float g_A2[1024 * 256];     // a' = x@Wg[:D] + bg
__device__ float g_B2[1024 * 256];     // b  = x@Wg[D:]
__device__ float g_paccv[512 * 256];   // per (b,ib,jh) partial: sum rs*v_h
__device__ float g_psrm[512];          // per (b,ib,jh) partial: sum rs*m
__device__ float g_rel[4 * 256];       // final rel vector per batch

// ---------------------------------------------------------------------------
// Kernel A: a' = x @ Wg[:256] + bg ; b = x @ Wg[256:]
// grid (128, 2), block 256. 8 rows x 256 cols per block, FFMA2 over row pairs.
// ---------------------------------------------------------------------------
__global__ __launch_bounds__(256) void gemm_ab(const float* __restrict__ x,
                                               const float* __restrict__ Wg,
                                               const float* __restrict__ bg) {
    int z = blockIdx.y;
    int m0 = blockIdx.x * 8;
    const float* __restrict__ W = Wg + z * 65536;   // Wg[(z*256+d)*256 + h]
    __shared__ float xst[256][12];                  // d-major, 8 rows used
    int tid = threadIdx.x;
#pragma unroll
    for (int r = 0; r < 8; r++) xst[tid][r] = x[(m0 + r) * 256 + tid];
    __syncthreads();

    float bias = (z == 0) ? bg[tid] : 0.0f;
    u64 accp[4];
#pragma unroll
    for (int k = 0; k < 4; k++) accp[k] = pk2(bias, bias);

#pragma unroll 8
    for (int d = 0; d < 256; d++) {
        float w = W[d * 256 + tid];
        u64 wp = pk2(w, w);
        const u64* xr = reinterpret_cast<const u64*>(&xst[d][0]);
#pragma unroll
        for (int k = 0; k < 4; k++) accp[k] = fmax2p(xr[k], wp, accp[k]);
    }

    float* __restrict__ out = z ? g_B2 : g_A2;
#pragma unroll
    for (int k = 0; k < 4; k++) {
        float o0, o1;
        up2(accp[k], o0, o1);
        out[(m0 + 2 * k) * 256 + tid] = o0;
        out[(m0 + 2 * k + 1) * 256 + tid] = o1;
    }
}

// ---------------------------------------------------------------------------
// Kernel B: pair loop. grid (64 ib, 4 b, 2 jh), block 256 (8 warps).
// Warp = 4 groups of 8 lanes; group g handles pair (i, j), lane s owns 32 h
// in chunk layout h = (c*8+s)*4 .. +3 for chunk c (0..7). LN reduction =
// 3-step 8-lane butterfly shared across the 4 groups.
// ---------------------------------------------------------------------------
__global__ __launch_bounds__(256) void pair_kernel() {
    int ib = blockIdx.x;
    int b  = blockIdx.y;
    int jh = blockIdx.z;
    int warp = threadIdx.x >> 5;
    int lane = threadIdx.x & 31;
    int g = lane >> 3;     // group (selects j within quad)
    int s = lane & 7;      // sublane (selects h chunks)

    __shared__ float sa[4][256];   // 4 A rows for this i-tile
    {
        int t = threadIdx.x;       // 1024 floats via float4
        const float4* src =
            reinterpret_cast<const float4*>(g_A2 + (b * 256 + ib * 4) * 256);
        reinterpret_cast<float4*>(&sa[0][0])[t] = src[t];
    }
    __syncthreads();

    const ulonglong2* __restrict__ Bb =
        reinterpret_cast<const ulonglong2*>(g_B2 + b * 65536);

    u64 acc[16];
#pragma unroll
    for (int k = 0; k < 16; k++) acc[k] = 0ull;
    float srm = 0.0f;

    int jw = jh * 128 + warp * 16;
#pragma unroll 2
    for (int q = 0; q < 4; q++) {
        int j = jw + q * 4 + g;
        u64 bp[16];
        const ulonglong2* Br = Bb + j * 64 + s;    // chunk c at +c*8
#pragma unroll
        for (int c = 0; c < 8; c++) {
            ulonglong2 t = Br[c * 8];
            bp[2 * c] = t.x; bp[2 * c + 1] = t.y;
        }

#pragma unroll
        for (int ii = 0; ii < 4; ii++) {
            const ulonglong2* Ar =
                reinterpret_cast<const ulonglong2*>(&sa[ii][0]) + s;
            u64 vp[16];
#pragma unroll
            for (int c = 0; c < 8; c++) {
                ulonglong2 t = Ar[c * 8];
                vp[2 * c]     = addx2(t.x, bp[2 * c]);
                vp[2 * c + 1] = addx2(t.y, bp[2 * c + 1]);
            }
            // relu (FMNMX on alu pipe; pack/unpack are register renames)
#pragma unroll
            for (int k = 0; k < 16; k++) {
                float lo, hi; up2(vp[k], lo, hi);
                vp[k] = pk2(fmaxf(lo, 0.0f), fmaxf(hi, 0.0f));
            }
            // s2 = sum v^2 : 4 parallel chains of 4
            u64 q0 = mulx2(vp[0], vp[0]);
            u64 q1 = mulx2(vp[1], vp[1]);
            u64 q2 = mulx2(vp[2], vp[2]);
            u64 q3 = mulx2(vp[3], vp[3]);
#pragma unroll
            for (int k = 4; k < 16; k += 4) {
                q0 = fmax2p(vp[k],     vp[k],     q0);
                q1 = fmax2p(vp[k + 1], vp[k + 1], q1);
                q2 = fmax2p(vp[k + 2], vp[k + 2], q2);
                q3 = fmax2p(vp[k + 3], vp[k + 3], q3);
            }
            u64 s2p = addx2(addx2(q0, q1), addx2(q2, q3));
            // s1 = sum v : tree
            u64 t0 = addx2(vp[0], vp[1]),   t1 = addx2(vp[2], vp[3]);
            u64 t2 = addx2(vp[4], vp[5]),   t3 = addx2(vp[6], vp[7]);
            u64 t4 = addx2(vp[8], vp[9]),   t5 = addx2(vp[10], vp[11]);
            u64 t6 = addx2(vp[12], vp[13]), t7 = addx2(vp[14], vp[15]);
            t0 = addx2(t0, t1); t2 = addx2(t2, t3);
            t4 = addx2(t4, t5); t6 = addx2(t6, t7);
            u64 s1p = addx2(addx2(t0, t2), addx2(t4, t6));

            float s1a, s1b; up2(s1p, s1a, s1b);
            float s2a, s2b; up2(s2p, s2a, s2b);
            u64 sv = pk2(s1a + s1b, s2a + s2b);
            // 3-step butterfly within the 8-lane group (shared by 4 groups)
            sv = addx2(sv, __shfl_xor_sync(0xffffffffu, sv, 1));
            sv = addx2(sv, __shfl_xor_sync(0xffffffffu, sv, 2));
            sv = addx2(sv, __shfl_xor_sync(0xffffffffu, sv, 4));
            float S1, S2; up2(sv, S1, S2);

            float m   = S1 * (1.0f / 256.0f);
            float var = fmaf(S2, 1.0f / 256.0f, -m * m);
            float rs  = rsqrtf(var + 1e-5f);
            u64 rsp = pk2(rs, rs);
#pragma unroll
            for (int k = 0; k < 16; k++) acc[k] = fmax2p(vp[k], rsp, acc[k]);
            srm = fmaf(rs, m, srm);
        }
    }

    // Reduce acc across the 4 groups (lanes differing in bits 3,4).
#pragma unroll
    for (int k = 0; k < 16; k++)
        acc[k] = addx2(acc[k], __shfl_xor_sync(0xffffffffu, acc[k], 8));
#pragma unroll
    for (int k = 0; k < 16; k++)
        acc[k] = addx2(acc[k], __shfl_xor_sync(0xffffffffu, acc[k], 16));
    // srm: each group's value replicated on 8 lanes -> full butterfly, /8.
#pragma unroll
    for (int off = 16; off > 0; off >>= 1)
        srm += __shfl_xor_sync(0xffffffffu, srm, off);

    __shared__ float sacc[8][256];
    __shared__ float ssrm[8];
    if (lane < 8) {
        float4* dst = reinterpret_cast<float4*>(&sacc[warp][0]) + lane;
#pragma unroll
        for (int c = 0; c < 8; c++) {
            float a0, a1, a2, a3;
            up2(acc[2 * c], a0, a1);
            up2(acc[2 * c + 1], a2, a3);
            dst[c * 8] = make_float4(a0, a1, a2, a3);   // h = (c*8+lane)*4
        }
        if (lane == 0) ssrm[warp] = srm * 0.125f;
    }
    __syncthreads();

    int tid = threadIdx.x;
    float tot = 0.0f;
#pragma unroll
    for (int w = 0; w < 8; w++) tot += sacc[w][tid];
    int p = (b * 64 + ib) * 2 + jh;
    g_paccv[p * 256 + tid] = tot;
    if (tid == 0) {
        float sm = 0.0f;
#pragma unroll
        for (int w = 0; w < 8; w++) sm += ssrm[w];
        g_psrm[p] = sm;
    }
}

// ---------------------------------------------------------------------------
// Kernel C: reduce partials -> r_sum, matvec with Wf, relu, LN -> g_rel.
// ---------------------------------------------------------------------------
__global__ __launch_bounds__(256) void finalize(const float* __restrict__ Wf,
                                                const float* __restrict__ bfv,
                                                const float* __restrict__ g_gamma,
                                                const float* __restrict__ g_beta,
                                                const float* __restrict__ f_gamma,
                                                const float* __restrict__ f_beta) {
    int b = blockIdx.x;
    int h = threadIdx.x;
    __shared__ float rsum[256];
    __shared__ float ssr[128];

    float av = 0.0f;
#pragma unroll 8
    for (int p = 0; p < 128; p++) av += g_paccv[(b * 128 + p) * 256 + h];
    if (h < 128) ssr[h] = g_psrm[b * 128 + h];
    __syncthreads();

    float srm = 0.0f;
#pragma unroll
    for (int q = 0; q < 128; q++) srm += ssr[q];

    rsum[h] = g_gamma[h] * (av - srm) + 65536.0f * g_beta[h];
    __syncthreads();

    float y = bfv[h];
#pragma unroll 8
    for (int d = 0; d < 256; d++) y = fmaf(rsum[d], Wf[d * 256 + h], y);
    y = fmaxf(y, 0.0f);

    float s1 = y, s2 = y * y;
#pragma unroll
    for (int off = 16; off > 0; off >>= 1) {
        s1 += __shfl_xor_sync(0xffffffffu, s1, off);
        s2 += __shfl_xor_sync(0xffffffffu, s2, off);
    }
    __shared__ float w1[8], w2[8];
    int warp = h >> 5, lane = h & 31;
    if (lane == 0) { w1[warp] = s1; w2[warp] = s2; }
    __syncthreads();
    float S1 = 0.0f, S2 = 0.0f;
#pragma unroll
    for (int w = 0; w < 8; w++) { S1 += w1[w]; S2 += w2[w]; }
    float m = S1 * (1.0f / 256.0f);
    float var = fmaf(S2, 1.0f / 256.0f, -m * m);
    float rs = rsqrtf(var + 1e-5f);
    g_rel[b * 256 + h] = (y - m) * rs * f_gamma[h] + f_beta[h];
}

// ---------------------------------------------------------------------------
// Kernel D: out[b,n,:] = rel[b,:] + x[b,n,:]
// ---------------------------------------------------------------------------
__global__ __launch_bounds__(128) void add_out(const float* __restrict__ x,
                                               float* __restrict__ out) {
    int i4 = blockIdx.x * 128 + threadIdx.x;  // 0..65535 float4s
    int base = i4 * 4;
    int b = base >> 16;
    int d = base & 255;
    float4 xv = reinterpret_cast<const float4*>(x)[i4];
    float4 rv = *reinterpret_cast<const float4*>(g_rel + b * 256 + d);
    float4 o;
    o.x = xv.x + rv.x;
    o.y = xv.y + rv.y;
    o.z = xv.z + rv.z;
    o.w = xv.w + rv.w;
    reinterpret_cast<float4*>(out)[i4] = o;
}

// ---------------------------------------------------------------------------
extern "C" void kernel_launch(void* const* d_in, const int* in_sizes, int n_in,
                              void* d_out, int out_size) {
    const float* x       = (const float*)d_in[0];
    const float* Wg      = (const float*)d_in[1];
    const float* bg      = (const float*)d_in[2];
    const float* g_gamma = (const float*)d_in[3];
    const float* g_beta  = (const float*)d_in[4];
    const float* Wf      = (const float*)d_in[5];
    const float* bf      = (const float*)d_in[6];
    const float* f_gamma = (const float*)d_in[7];
    const float* f_beta  = (const float*)d_in[8];
    float* out = (float*)d_out;

    gemm_ab<<<dim3(128, 2), 256>>>(x, Wg, bg);
    pair_kernel<<<dim3(64, 4, 2), 256>>>();
    finalize<<<4, 256>>>(Wf, bf, g_gamma, g_beta, f_gamma, f_beta);
    add_out<<<512, 128>>>(x, out);
}